// round 1
// baseline (speedup 1.0000x reference)
#include <cuda_runtime.h>
#include <math.h>

#define D_MODEL   2048
#define D_INNER   4096
#define D_STATE   128
#define D_CONV    4
#define HEADDIM   64
#define NHEADS    64
#define CONV_DIM  4352     /* D_INNER + 2*D_STATE */
#define D_IN_PROJ 8512     /* 2*D_INNER + 2*D_STATE + NHEADS */
#define BATCH     2
#define TLEN      2048
#define NTOK      (BATCH*TLEN)   /* 4096 */
#define RMS_EPS   1e-5f

// ---------------- scratch (device globals; no allocs allowed) ----------------
__device__ float g_zx [(size_t)NTOK * D_IN_PROJ];   // in_proj output  (139 MB)
__device__ float g_xbc[(size_t)NTOK * CONV_DIM];    // conv+silu output (71 MB)
__device__ float g_y  [(size_t)NTOK * D_INNER];     // scan / gated+normed y (67 MB)

// ---------------- generic NT SGEMM: C[M,N] = A[M,K] * B[N,K]^T ----------------
// 128x128 tile, BK=8, 256 threads, 8x8 per thread.
__global__ void __launch_bounds__(256) sgemm_nt_kernel(
    const float* __restrict__ A, const float* __restrict__ B,
    float* __restrict__ C, int M, int N, int K)
{
    __shared__ __align__(16) float As[8][132];   // 132: pad keeps 16B align (528B rows) + no STS conflict
    __shared__ __align__(16) float Bs[8][132];

    const int tid  = threadIdx.x;
    const int bm   = blockIdx.y * 128;
    const int bn   = blockIdx.x * 128;
    const int lrow = tid >> 1;            // 0..127
    const int lk   = (tid & 1) << 2;      // 0 or 4
    const int tx   = tid & 15;            // col group
    const int ty   = tid >> 4;            // row group

    float acc[8][8];
#pragma unroll
    for (int i = 0; i < 8; ++i)
#pragma unroll
        for (int j = 0; j < 8; ++j) acc[i][j] = 0.f;

    for (int k0 = 0; k0 < K; k0 += 8) {
        float4 av = make_float4(0.f,0.f,0.f,0.f);
        float4 bv = make_float4(0.f,0.f,0.f,0.f);
        const int ar = bm + lrow;
        const int br = bn + lrow;
        if (ar < M) av = *(const float4*)(A + (size_t)ar * K + k0 + lk);
        if (br < N) bv = *(const float4*)(B + (size_t)br * K + k0 + lk);

        __syncthreads();
        As[lk+0][lrow] = av.x; As[lk+1][lrow] = av.y;
        As[lk+2][lrow] = av.z; As[lk+3][lrow] = av.w;
        Bs[lk+0][lrow] = bv.x; Bs[lk+1][lrow] = bv.y;
        Bs[lk+2][lrow] = bv.z; Bs[lk+3][lrow] = bv.w;
        __syncthreads();

#pragma unroll
        for (int kk = 0; kk < 8; ++kk) {
            float a[8], b[8];
            *(float4*)&a[0] = *(const float4*)&As[kk][ty*8];
            *(float4*)&a[4] = *(const float4*)&As[kk][ty*8+4];
            *(float4*)&b[0] = *(const float4*)&Bs[kk][tx*8];
            *(float4*)&b[4] = *(const float4*)&Bs[kk][tx*8+4];
#pragma unroll
            for (int i = 0; i < 8; ++i)
#pragma unroll
                for (int j = 0; j < 8; ++j)
                    acc[i][j] += a[i] * b[j];
        }
    }

#pragma unroll
    for (int i = 0; i < 8; ++i) {
        const int row = bm + ty*8 + i;
        if (row >= M) continue;
        float* Crow = C + (size_t)row * N;
        const int col = bn + tx*8;
        if (col < N)
            *(float4*)(Crow + col) = make_float4(acc[i][0], acc[i][1], acc[i][2], acc[i][3]);
        if (col + 4 < N)
            *(float4*)(Crow + col + 4) = make_float4(acc[i][4], acc[i][5], acc[i][6], acc[i][7]);
    }
}

// ---------------- depthwise causal conv (width 4) + SiLU ----------------
// xBC = zx[:, :, D_INNER : D_INNER+CONV_DIM]; out[b,t,c] = silu(bias + sum_k x[t-3+k]*w[c,k])
__global__ void __launch_bounds__(256) conv_silu_kernel(
    const float* __restrict__ cw, const float* __restrict__ cb)
{
    const int c  = blockIdx.x * 256 + threadIdx.x;   // CONV_DIM = 17*256
    const int b  = blockIdx.z;
    const int t0 = blockIdx.y * 32;

    const float w0 = cw[c*4+0], w1 = cw[c*4+1], w2 = cw[c*4+2], w3 = cw[c*4+3];
    const float bias = cb[c];

    const float* base = g_zx + ((size_t)b * TLEN) * D_IN_PROJ + D_INNER + c;
    float* ob = g_xbc + ((size_t)b * TLEN) * CONV_DIM + c;

    float x0 = (t0 >= 3) ? base[(size_t)(t0-3) * D_IN_PROJ] : 0.f;
    float x1 = (t0 >= 2) ? base[(size_t)(t0-2) * D_IN_PROJ] : 0.f;
    float x2 = (t0 >= 1) ? base[(size_t)(t0-1) * D_IN_PROJ] : 0.f;

    for (int t = t0; t < t0 + 32; ++t) {
        const float x3 = base[(size_t)t * D_IN_PROJ];
        const float v  = bias + x0*w0 + x1*w1 + x2*w2 + x3*w3;
        ob[(size_t)t * CONV_DIM] = v / (1.f + expf(-v));
        x0 = x1; x1 = x2; x2 = x3;
    }
}

// ---------------- SSM scan ----------------
// One block per (h, b). 128 threads: thread = p*2 + half; each owns h[p][half*64 .. +64) in regs.
#define SCAN_TC 8
__global__ void __launch_bounds__(128) scan_kernel(
    const float* __restrict__ dt_bias, const float* __restrict__ A_log,
    const float* __restrict__ Dskip)
{
    const int h   = blockIdx.x;
    const int b   = blockIdx.y;
    const int tid = threadIdx.x;
    const int p    = tid >> 1;
    const int half = tid & 1;
    const int nb   = half * 64;

    __shared__ __align__(16) float sB[SCAN_TC][128];
    __shared__ __align__(16) float sC[SCAN_TC][128];
    __shared__ __align__(16) float sX[SCAN_TC][64];
    __shared__ float sDA[SCAN_TC], sDT[SCAN_TC];

    float4 hst[16];
#pragma unroll
    for (int q = 0; q < 16; ++q) hst[q] = make_float4(0.f,0.f,0.f,0.f);

    const float Acoef = -expf(A_log[h]);
    const float dtb   = dt_bias[h];
    const float dsk   = Dskip[h];

    const float* xbc_b    = g_xbc + (size_t)b * TLEN * CONV_DIM;
    const float* dtr_base = g_zx  + (size_t)b * TLEN * D_IN_PROJ + (D_INNER + CONV_DIM) + h;
    float*       y_base   = g_y   + (size_t)b * TLEN * D_INNER + h * HEADDIM;

    for (int t0 = 0; t0 < TLEN; t0 += SCAN_TC) {
#pragma unroll
        for (int tl = 0; tl < SCAN_TC; ++tl) {
            const float* row = xbc_b + (size_t)(t0 + tl) * CONV_DIM;
            sB[tl][tid] = row[D_INNER + tid];
            sC[tl][tid] = row[D_INNER + D_STATE + tid];
            if (tid < 64) sX[tl][tid] = row[h * HEADDIM + tid];
        }
        if (tid < SCAN_TC) {
            const float raw = dtr_base[(size_t)(t0 + tid) * D_IN_PROJ] + dtb;
            const float dt  = (raw > 20.f) ? raw : log1pf(expf(raw));
            sDT[tid] = dt;
            sDA[tid] = expf(dt * Acoef);
        }
        __syncthreads();

#pragma unroll
        for (int tl = 0; tl < SCAN_TC; ++tl) {
            const float dA  = sDA[tl];
            const float dtx = sDT[tl] * sX[tl][p];
            const float4* B4 = (const float4*)&sB[tl][nb];
            const float4* C4 = (const float4*)&sC[tl][nb];
            float y = 0.f;
#pragma unroll
            for (int q = 0; q < 16; ++q) {
                const float4 bb = B4[q];
                const float4 cc = C4[q];
                hst[q].x = hst[q].x * dA + dtx * bb.x;  y += hst[q].x * cc.x;
                hst[q].y = hst[q].y * dA + dtx * bb.y;  y += hst[q].y * cc.y;
                hst[q].z = hst[q].z * dA + dtx * bb.z;  y += hst[q].z * cc.z;
                hst[q].w = hst[q].w * dA + dtx * bb.w;  y += hst[q].w * cc.w;
            }
            y += __shfl_xor_sync(0xffffffffu, y, 1);
            if (half == 0) {
                y += dsk * sX[tl][p];
                y_base[(size_t)(t0 + tl) * D_INNER + p] = y;
            }
        }
        __syncthreads();
    }
}

// ---------------- gate (y * silu(z)) + RMSNorm, in place on g_y ----------------
__global__ void __launch_bounds__(256) gate_norm_kernel(const float* __restrict__ nw)
{
    const int row = blockIdx.x;
    const int tid = threadIdx.x;
    const float* zrow = g_zx + (size_t)row * D_IN_PROJ;   // z = first D_INNER
    float*       yrow = g_y  + (size_t)row * D_INNER;

    float g[16];
    float ss = 0.f;
#pragma unroll
    for (int i = 0; i < 4; ++i) {
        const int e = i * 1024 + tid * 4;
        const float4 yv = *(const float4*)(yrow + e);
        const float4 zv = *(const float4*)(zrow + e);
        float g0 = yv.x * (zv.x / (1.f + expf(-zv.x)));
        float g1 = yv.y * (zv.y / (1.f + expf(-zv.y)));
        float g2 = yv.z * (zv.z / (1.f + expf(-zv.z)));
        float g3 = yv.w * (zv.w / (1.f + expf(-zv.w)));
        g[i*4+0] = g0; g[i*4+1] = g1; g[i*4+2] = g2; g[i*4+3] = g3;
        ss += g0*g0 + g1*g1 + g2*g2 + g3*g3;
    }

    // block reduce ss
    ss += __shfl_xor_sync(0xffffffffu, ss, 16);
    ss += __shfl_xor_sync(0xffffffffu, ss, 8);
    ss += __shfl_xor_sync(0xffffffffu, ss, 4);
    ss += __shfl_xor_sync(0xffffffffu, ss, 2);
    ss += __shfl_xor_sync(0xffffffffu, ss, 1);
    __shared__ float red[8];
    if ((tid & 31) == 0) red[tid >> 5] = ss;
    __syncthreads();
    float tot = 0.f;
#pragma unroll
    for (int w = 0; w < 8; ++w) tot += red[w];

    const float scale = rsqrtf(tot / (float)D_INNER + RMS_EPS);
#pragma unroll
    for (int i = 0; i < 4; ++i) {
        const int e = i * 1024 + tid * 4;
        float4 o;
        o.x = g[i*4+0] * scale * nw[e+0];
        o.y = g[i*4+1] * scale * nw[e+1];
        o.z = g[i*4+2] * scale * nw[e+2];
        o.w = g[i*4+3] * scale * nw[e+3];
        *(float4*)(yrow + e) = o;
    }
}

// ---------------- launch ----------------
extern "C" void kernel_launch(void* const* d_in, const int* in_sizes, int n_in,
                              void* d_out, int out_size)
{
    const float* x          = (const float*)d_in[0];
    // d_in[1]=cos, d_in[2]=sin : unused by reference
    const float* in_proj_w  = (const float*)d_in[3];
    const float* conv_w     = (const float*)d_in[4];
    const float* conv_b     = (const float*)d_in[5];
    const float* dt_bias    = (const float*)d_in[6];
    const float* A_log      = (const float*)d_in[7];
    const float* Dskip      = (const float*)d_in[8];
    const float* norm_w     = (const float*)d_in[9];
    const float* out_proj_w = (const float*)d_in[10];
    float* out = (float*)d_out;

    float *zx, *xbc, *y;
    cudaGetSymbolAddress((void**)&zx,  g_zx);
    cudaGetSymbolAddress((void**)&xbc, g_xbc);
    cudaGetSymbolAddress((void**)&y,   g_y);

    // 1) in_proj: zx[4096, 8512] = x[4096,2048] * W[8512,2048]^T
    {
        dim3 grid((D_IN_PROJ + 127) / 128, NTOK / 128);
        sgemm_nt_kernel<<<grid, 256>>>(x, in_proj_w, zx, NTOK, D_IN_PROJ, D_MODEL);
    }
    // 2) conv + silu
    {
        dim3 grid(CONV_DIM / 256, TLEN / 32, BATCH);
        conv_silu_kernel<<<grid, 256>>>(conv_w, conv_b);
    }
    // 3) SSM scan
    {
        dim3 grid(NHEADS, BATCH);
        scan_kernel<<<grid, 128>>>(dt_bias, A_log, Dskip);
    }
    // 4) gate + RMSNorm (in place on g_y)
    gate_norm_kernel<<<NTOK, 256>>>(norm_w);

    // 5) out_proj: out[4096, 2048] = y[4096,4096] * Wout[2048,4096]^T
    {
        dim3 grid(D_MODEL / 128, NTOK / 128);
        sgemm_nt_kernel<<<grid, 256>>>(y, out_proj_w, out, NTOK, D_MODEL, D_INNER);
    }
}

// round 3
// speedup vs baseline: 1.4694x; 1.4694x over previous
#include <cuda_runtime.h>
#include <math.h>
#include <stdint.h>

#define D_MODEL   2048
#define D_INNER   4096
#define D_STATE   128
#define HEADDIM   64
#define NHEADS    64
#define CONV_DIM  4352     /* D_INNER + 2*D_STATE */
#define D_IN_PROJ 8512     /* 2*D_INNER + 2*D_STATE + NHEADS */
#define BATCH     2
#define TLEN      2048
#define NTOK      (BATCH*TLEN)   /* 4096 */
#define RMS_EPS   1e-5f

// ---------------- scratch (device globals; no allocs allowed) ----------------
__device__ float g_zx [(size_t)NTOK * D_IN_PROJ];   // in_proj output
__device__ float g_xbc[(size_t)NTOK * CONV_DIM];    // conv+silu output
__device__ float g_y  [(size_t)NTOK * D_INNER];     // scan / gated+normed y

__device__ __forceinline__ uint32_t smem_to_u32(const void* p) {
    uint32_t a;
    asm("{ .reg .u64 t; cvta.to.shared.u64 t, %1; cvt.u32.u64 %0, t; }" : "=r"(a) : "l"(p));
    return a;
}

// ======================= tf32x3 GEMM via mma.sync (compute_103-safe) =======================
// C[M,N] = A[M,K] * B[N,K]^T, fp32 in/out.
// fp32-level accuracy: a = ah + al (ah = top-10-mantissa), acc += ah*bh + ah*bl + al*bh.
// 128x128x32 tile, 256 threads = 8 warps (2 M x 4 N), warp tile 64x32.
// Double-buffered SMEM via cp.async; pad rows to 36 floats (conflict-free frag loads).

#define PADK 36
#define TILE_FLT (128 * PADK)      /* 4608 floats per tile */
#define GEMM_SMEM (4 * TILE_FLT * 4)  /* 2 stages x (A+B) = 73728 B */

__device__ __forceinline__ void mma1688(float* c, const uint32_t* a, const uint32_t* b) {
    asm volatile(
        "mma.sync.aligned.m16n8k8.row.col.f32.tf32.tf32.f32 "
        "{%0,%1,%2,%3}, {%4,%5,%6,%7}, {%8,%9}, {%0,%1,%2,%3};"
        : "+f"(c[0]), "+f"(c[1]), "+f"(c[2]), "+f"(c[3])
        : "r"(a[0]), "r"(a[1]), "r"(a[2]), "r"(a[3]), "r"(b[0]), "r"(b[1]));
}

__global__ void __launch_bounds__(256, 1) mma_gemm_tf32x3(
    const float* __restrict__ A, const float* __restrict__ B,
    float* __restrict__ C, int M, int N, int K)
{
    extern __shared__ float sm[];
    const int tid  = threadIdx.x;
    const int wid  = tid >> 5;
    const int lane = tid & 31;
    const int g    = lane >> 2;       // group id 0..7
    const int tig  = lane & 3;        // thread-in-group
    const int bm   = blockIdx.x * 128;
    const int bn   = blockIdx.y * 128;
    const int wm   = (wid & 1) * 64;
    const int wn   = (wid >> 1) * 32;

    const uint32_t sbase = smem_to_u32(sm);

    float acc[4][4][4];
#pragma unroll
    for (int mt = 0; mt < 4; ++mt)
#pragma unroll
        for (int nt = 0; nt < 4; ++nt)
#pragma unroll
            for (int q = 0; q < 4; ++q) acc[mt][nt][q] = 0.f;

    const int NC = K >> 5;   // BK = 32

    // ---- stage loader: 1024 float4 per (A,B) pair, 4 per thread each ----
    auto load_stage = [&](int s, int c) {
        const int kb = c * 32;
#pragma unroll
        for (int i = 0; i < 4; ++i) {
            const int f   = tid + 256 * i;        // 0..1023
            const int row = f >> 3;               // 0..127
            const int c4  = (f & 7) * 4;          // 0,4,..28
            // A (rows always valid: M multiple of 128)
            {
                const float* gp = A + (size_t)(bm + row) * K + kb + c4;
                const uint32_t sa = sbase + (uint32_t)(s * TILE_FLT + row * PADK + c4) * 4u;
                asm volatile("cp.async.cg.shared.global [%0], [%1], 16;"
                             :: "r"(sa), "l"(gp) : "memory");
            }
            // B (row may exceed N; zero-fill via src-size 0)
            {
                const int brow = bn + row;
                const int safe = (brow < N) ? brow : 0;
                const float* gp = B + (size_t)safe * K + kb + c4;
                const uint32_t sa = sbase + (uint32_t)(2 * TILE_FLT + s * TILE_FLT + row * PADK + c4) * 4u;
                const uint32_t sz = (brow < N) ? 16u : 0u;
                asm volatile("cp.async.cg.shared.global [%0], [%1], 16, %2;"
                             :: "r"(sa), "l"(gp), "r"(sz) : "memory");
            }
        }
        asm volatile("cp.async.commit_group;" ::: "memory");
    };

    auto compute_stage = [&](int s) {
        const float* As_ = sm + s * TILE_FLT;
        const float* Bs_ = sm + 2 * TILE_FLT + s * TILE_FLT;
#pragma unroll
        for (int ks = 0; ks < 4; ++ks) {
            const int k0 = ks * 8;
            uint32_t ah[4][4], al[4][4];
#pragma unroll
            for (int mt = 0; mt < 4; ++mt) {
                const int r = wm + mt * 16;
                float v[4];
                v[0] = As_[(r + g)     * PADK + k0 + tig];
                v[1] = As_[(r + g + 8) * PADK + k0 + tig];
                v[2] = As_[(r + g)     * PADK + k0 + tig + 4];
                v[3] = As_[(r + g + 8) * PADK + k0 + tig + 4];
#pragma unroll
                for (int q = 0; q < 4; ++q) {
                    const uint32_t h = __float_as_uint(v[q]) & 0xFFFFE000u;
                    ah[mt][q] = h;
                    al[mt][q] = __float_as_uint(v[q] - __uint_as_float(h));
                }
            }
            uint32_t bh[4][2], bl[4][2];
#pragma unroll
            for (int nt = 0; nt < 4; ++nt) {
                const int r = wn + nt * 8;
                float v0 = Bs_[(r + g) * PADK + k0 + tig];
                float v1 = Bs_[(r + g) * PADK + k0 + tig + 4];
                uint32_t h0 = __float_as_uint(v0) & 0xFFFFE000u;
                uint32_t h1 = __float_as_uint(v1) & 0xFFFFE000u;
                bh[nt][0] = h0; bh[nt][1] = h1;
                bl[nt][0] = __float_as_uint(v0 - __uint_as_float(h0));
                bl[nt][1] = __float_as_uint(v1 - __uint_as_float(h1));
            }
#pragma unroll
            for (int mt = 0; mt < 4; ++mt)
#pragma unroll
                for (int nt = 0; nt < 4; ++nt) {
                    mma1688(acc[mt][nt], ah[mt], bh[nt]);
                    mma1688(acc[mt][nt], ah[mt], bl[nt]);
                    mma1688(acc[mt][nt], al[mt], bh[nt]);
                }
        }
    };

    // ---- pipelined main loop ----
    load_stage(0, 0);
    for (int c = 0; c < NC; ++c) {
        if (c + 1 < NC) {
            load_stage((c + 1) & 1, c + 1);
            asm volatile("cp.async.wait_group 1;" ::: "memory");
        } else {
            asm volatile("cp.async.wait_group 0;" ::: "memory");
        }
        __syncthreads();
        compute_stage(c & 1);
        __syncthreads();
    }

    // ---- epilogue: direct GMEM stores (float2 per fragment row) ----
#pragma unroll
    for (int mt = 0; mt < 4; ++mt) {
        const int row0 = bm + wm + mt * 16 + g;
#pragma unroll
        for (int nt = 0; nt < 4; ++nt) {
            const int col = bn + wn + nt * 8 + tig * 2;
            if (col < N) {
                *(float2*)(C + (size_t)row0 * N + col)       = make_float2(acc[mt][nt][0], acc[mt][nt][1]);
                *(float2*)(C + (size_t)(row0 + 8) * N + col) = make_float2(acc[mt][nt][2], acc[mt][nt][3]);
            }
        }
    }
}

// ---------------- depthwise causal conv (width 4) + SiLU ----------------
__global__ void __launch_bounds__(256) conv_silu_kernel(
    const float* __restrict__ cw, const float* __restrict__ cb)
{
    const int c  = blockIdx.x * 256 + threadIdx.x;
    const int b  = blockIdx.z;
    const int t0 = blockIdx.y * 32;

    const float w0 = cw[c*4+0], w1 = cw[c*4+1], w2 = cw[c*4+2], w3 = cw[c*4+3];
    const float bias = cb[c];

    const float* base = g_zx + ((size_t)b * TLEN) * D_IN_PROJ + D_INNER + c;
    float* ob = g_xbc + ((size_t)b * TLEN) * CONV_DIM + c;

    float x0 = (t0 >= 3) ? base[(size_t)(t0-3) * D_IN_PROJ] : 0.f;
    float x1 = (t0 >= 2) ? base[(size_t)(t0-2) * D_IN_PROJ] : 0.f;
    float x2 = (t0 >= 1) ? base[(size_t)(t0-1) * D_IN_PROJ] : 0.f;

    for (int t = t0; t < t0 + 32; ++t) {
        const float x3 = base[(size_t)t * D_IN_PROJ];
        const float v  = bias + x0*w0 + x1*w1 + x2*w2 + x3*w3;
        ob[(size_t)t * CONV_DIM] = v / (1.f + expf(-v));
        x0 = x1; x1 = x2; x2 = x3;
    }
}

// ---------------- SSM scan ----------------
#define SCAN_TC 8
__global__ void __launch_bounds__(128) scan_kernel(
    const float* __restrict__ dt_bias, const float* __restrict__ A_log,
    const float* __restrict__ Dskip)
{
    const int h   = blockIdx.x;
    const int b   = blockIdx.y;
    const int tid = threadIdx.x;
    const int p    = tid >> 1;
    const int half = tid & 1;
    const int nb   = half * 64;

    __shared__ __align__(16) float sB[SCAN_TC][128];
    __shared__ __align__(16) float sC[SCAN_TC][128];
    __shared__ __align__(16) float sX[SCAN_TC][64];
    __shared__ float sDA[SCAN_TC], sDT[SCAN_TC];

    float4 hst[16];
#pragma unroll
    for (int q = 0; q < 16; ++q) hst[q] = make_float4(0.f,0.f,0.f,0.f);

    const float Acoef = -expf(A_log[h]);
    const float dtb   = dt_bias[h];
    const float dsk   = Dskip[h];

    const float* xbc_b    = g_xbc + (size_t)b * TLEN * CONV_DIM;
    const float* dtr_base = g_zx  + (size_t)b * TLEN * D_IN_PROJ + (D_INNER + CONV_DIM) + h;
    float*       y_base   = g_y   + (size_t)b * TLEN * D_INNER + h * HEADDIM;

    for (int t0 = 0; t0 < TLEN; t0 += SCAN_TC) {
#pragma unroll
        for (int tl = 0; tl < SCAN_TC; ++tl) {
            const float* row = xbc_b + (size_t)(t0 + tl) * CONV_DIM;
            sB[tl][tid] = row[D_INNER + tid];
            sC[tl][tid] = row[D_INNER + D_STATE + tid];
            if (tid < 64) sX[tl][tid] = row[h * HEADDIM + tid];
        }
        if (tid < SCAN_TC) {
            const float raw = dtr_base[(size_t)(t0 + tid) * D_IN_PROJ] + dtb;
            const float dt  = (raw > 20.f) ? raw : log1pf(expf(raw));
            sDT[tid] = dt;
            sDA[tid] = expf(dt * Acoef);
        }
        __syncthreads();

#pragma unroll
        for (int tl = 0; tl < SCAN_TC; ++tl) {
            const float dA  = sDA[tl];
            const float dtx = sDT[tl] * sX[tl][p];
            const float4* B4 = (const float4*)&sB[tl][nb];
            const float4* C4 = (const float4*)&sC[tl][nb];
            float y = 0.f;
#pragma unroll
            for (int q = 0; q < 16; ++q) {
                const float4 bb = B4[q];
                const float4 cc = C4[q];
                hst[q].x = hst[q].x * dA + dtx * bb.x;  y += hst[q].x * cc.x;
                hst[q].y = hst[q].y * dA + dtx * bb.y;  y += hst[q].y * cc.y;
                hst[q].z = hst[q].z * dA + dtx * bb.z;  y += hst[q].z * cc.z;
                hst[q].w = hst[q].w * dA + dtx * bb.w;  y += hst[q].w * cc.w;
            }
            y += __shfl_xor_sync(0xffffffffu, y, 1);
            if (half == 0) {
                y += dsk * sX[tl][p];
                y_base[(size_t)(t0 + tl) * D_INNER + p] = y;
            }
        }
        __syncthreads();
    }
}

// ---------------- gate (y * silu(z)) + RMSNorm, in place on g_y ----------------
__global__ void __launch_bounds__(256) gate_norm_kernel(const float* __restrict__ nw)
{
    const int row = blockIdx.x;
    const int tid = threadIdx.x;
    const float* zrow = g_zx + (size_t)row * D_IN_PROJ;
    float*       yrow = g_y  + (size_t)row * D_INNER;

    float g[16];
    float ss = 0.f;
#pragma unroll
    for (int i = 0; i < 4; ++i) {
        const int e = i * 1024 + tid * 4;
        const float4 yv = *(const float4*)(yrow + e);
        const float4 zv = *(const float4*)(zrow + e);
        float g0 = yv.x * (zv.x / (1.f + expf(-zv.x)));
        float g1 = yv.y * (zv.y / (1.f + expf(-zv.y)));
        float g2 = yv.z * (zv.z / (1.f + expf(-zv.z)));
        float g3 = yv.w * (zv.w / (1.f + expf(-zv.w)));
        g[i*4+0] = g0; g[i*4+1] = g1; g[i*4+2] = g2; g[i*4+3] = g3;
        ss += g0*g0 + g1*g1 + g2*g2 + g3*g3;
    }

    ss += __shfl_xor_sync(0xffffffffu, ss, 16);
    ss += __shfl_xor_sync(0xffffffffu, ss, 8);
    ss += __shfl_xor_sync(0xffffffffu, ss, 4);
    ss += __shfl_xor_sync(0xffffffffu, ss, 2);
    ss += __shfl_xor_sync(0xffffffffu, ss, 1);
    __shared__ float red[8];
    if ((tid & 31) == 0) red[tid >> 5] = ss;
    __syncthreads();
    float tot = 0.f;
#pragma unroll
    for (int w = 0; w < 8; ++w) tot += red[w];

    const float scale = rsqrtf(tot / (float)D_INNER + RMS_EPS);
#pragma unroll
    for (int i = 0; i < 4; ++i) {
        const int e = i * 1024 + tid * 4;
        float4 o;
        o.x = g[i*4+0] * scale * nw[e+0];
        o.y = g[i*4+1] * scale * nw[e+1];
        o.z = g[i*4+2] * scale * nw[e+2];
        o.w = g[i*4+3] * scale * nw[e+3];
        *(float4*)(yrow + e) = o;
    }
}

// ---------------- launch ----------------
extern "C" void kernel_launch(void* const* d_in, const int* in_sizes, int n_in,
                              void* d_out, int out_size)
{
    const float* x          = (const float*)d_in[0];
    const float* in_proj_w  = (const float*)d_in[3];
    const float* conv_w     = (const float*)d_in[4];
    const float* conv_b     = (const float*)d_in[5];
    const float* dt_bias    = (const float*)d_in[6];
    const float* A_log      = (const float*)d_in[7];
    const float* Dskip      = (const float*)d_in[8];
    const float* norm_w     = (const float*)d_in[9];
    const float* out_proj_w = (const float*)d_in[10];
    float* out = (float*)d_out;

    float *zx, *y;
    cudaGetSymbolAddress((void**)&zx, g_zx);
    cudaGetSymbolAddress((void**)&y,  g_y);

    cudaFuncSetAttribute(mma_gemm_tf32x3,
                         cudaFuncAttributeMaxDynamicSharedMemorySize, GEMM_SMEM);

    // 1) in_proj: zx[4096, 8512] = x[4096,2048] * W[8512,2048]^T
    {
        dim3 grid(NTOK / 128, (D_IN_PROJ + 127) / 128);
        mma_gemm_tf32x3<<<grid, 256, GEMM_SMEM>>>(x, in_proj_w, zx, NTOK, D_IN_PROJ, D_MODEL);
    }
    // 2) conv + silu
    {
        dim3 grid(CONV_DIM / 256, TLEN / 32, BATCH);
        conv_silu_kernel<<<grid, 256>>>(conv_w, conv_b);
    }
    // 3) SSM scan
    {
        dim3 grid(NHEADS, BATCH);
        scan_kernel<<<grid, 128>>>(dt_bias, A_log, Dskip);
    }
    // 4) gate + RMSNorm
    gate_norm_kernel<<<NTOK, 256>>>(norm_w);

    // 5) out_proj: out[4096, 2048] = y[4096,4096] * Wout[2048,4096]^T
    {
        dim3 grid(NTOK / 128, D_MODEL / 128);
        mma_gemm_tf32x3<<<grid, 256, GEMM_SMEM>>>(y, out_proj_w, out, NTOK, D_MODEL, D_INNER);
    }
}